// round 1
// baseline (speedup 1.0000x reference)
#include <cuda_runtime.h>
#include <math.h>

#define UNITS 1536
#define NZ (4 * UNITS)          // 6144 gate pre-activations per LSTM
#define NSPLIT 32               // k-splits per GEMV
#define CHAR_LEN 256
#define VOCAB 80
#define N_MIX 10

// ---------------- device scratch (no allocations allowed) ----------------
__device__ float g_part[NSPLIT][NZ];          // split-K partial sums
__device__ float g_x1[3 + VOCAB];             // [inputs, w_prev]          (83)
__device__ float g_x2[3 + VOCAB + UNITS];     // [inputs, w, h1n]          (1619)
__device__ float g_x3[3 + VOCAB + UNITS];     // [inputs, w, h2n]          (1619)

__device__ __forceinline__ float sigf(float x) { return 1.0f / (1.0f + expf(-x)); }

// ---------------- tiny prep: build x1 head and input heads ----------------
__global__ void prep_kernel(const float* __restrict__ inputs,
                            const float* __restrict__ w_prev) {
    int t = threadIdx.x;
    if (t < 3) { g_x1[t] = inputs[t]; g_x2[t] = inputs[t]; g_x3[t] = inputs[t]; }
    if (t < VOCAB) g_x1[3 + t] = w_prev[t];
}

// ---------------- split-K GEMV over two stacked segments ----------------
// z[j] (j in 0..6143) partial = sum_{k in [k0,k1)} xcat[k] * Mcat[k][j]
// where Mcat = [A (Ka rows) ; B (Kb rows)], xcat = [xa ; xb].
// Each thread owns 4 consecutive columns (float4); warp reads are fully
// coalesced (128B per k-row per warp). Deterministic: partials land in
// g_part[split][*], reduced in fixed order by the gates kernel.
__global__ void __launch_bounds__(128) gemv_kernel(
    const float* __restrict__ A, const float* __restrict__ xa, int Ka,
    const float* __restrict__ B, const float* __restrict__ xb, int Kb)
{
    int col = blockIdx.x * blockDim.x + threadIdx.x;   // float4 column 0..1535
    int split = blockIdx.y;
    int Kt = Ka + Kb;
    int k0 = (Kt * split) / NSPLIT;
    int k1 = (Kt * (split + 1)) / NSPLIT;

    float4 acc = make_float4(0.f, 0.f, 0.f, 0.f);
    int k = k0;
    int ka_end = (k1 < Ka) ? k1 : Ka;

    #pragma unroll 4
    for (; k < ka_end; ++k) {
        float xv = __ldg(xa + k);
        float4 r = *reinterpret_cast<const float4*>(A + (size_t)k * NZ + col * 4);
        acc.x += xv * r.x; acc.y += xv * r.y; acc.z += xv * r.z; acc.w += xv * r.w;
    }
    #pragma unroll 4
    for (; k < k1; ++k) {
        int kb = k - Ka;
        float xv = __ldg(xb + kb);
        float4 r = *reinterpret_cast<const float4*>(B + (size_t)kb * NZ + col * 4);
        acc.x += xv * r.x; acc.y += xv * r.y; acc.z += xv * r.z; acc.w += xv * r.w;
    }
    *reinterpret_cast<float4*>(&g_part[split][col * 4]) = acc;
}

// ---------------- reduce partials + LSTM gates ----------------
// Keras gate order: i, f, g, o in blocks of UNITS.
__global__ void __launch_bounds__(128) gates_kernel(
    const float* __restrict__ b, const float* __restrict__ c_in,
    float* __restrict__ out_h, float* __restrict__ xnext)
{
    int u = blockIdx.x * blockDim.x + threadIdx.x;     // 0..1535
    float zi = b[u];
    float zf = b[u + UNITS];
    float zg = b[u + 2 * UNITS];
    float zo = b[u + 3 * UNITS];
    #pragma unroll
    for (int s = 0; s < NSPLIT; ++s) {
        zi += g_part[s][u];
        zf += g_part[s][u + UNITS];
        zg += g_part[s][u + 2 * UNITS];
        zo += g_part[s][u + 3 * UNITS];
    }
    float c = sigf(zf) * c_in[u] + sigf(zi) * tanhf(zg);
    float h = sigf(zo) * tanhf(c);
    out_h[u] = h;
    if (xnext) xnext[u] = h;
}

// ---------------- attention window (single block, 960 threads) ----------------
__global__ void __launch_bounds__(960) window_kernel(
    const float* __restrict__ Wd, const float* __restrict__ bd,
    const float* __restrict__ kappa_prev, const float* __restrict__ sentence)
{
    __shared__ float coef[30];
    __shared__ float alpha[N_MIX], beta[N_MIX], kap[N_MIX];
    __shared__ float phi[CHAR_LEN];

    const float* h1 = g_x2 + 3 + VOCAB;   // h1n lives in x2 tail
    int t = threadIdx.x;
    int warp = t >> 5, lane = t & 31;

    // coef[j] = h1n @ Wd[:, j] + bd[j], one warp per output (30 warps)
    if (warp < 30) {
        float acc = 0.f;
        for (int k = lane; k < UNITS; k += 32)
            acc += h1[k] * Wd[k * 30 + warp];
        #pragma unroll
        for (int o = 16; o; o >>= 1) acc += __shfl_down_sync(0xffffffffu, acc, o);
        if (lane == 0) coef[warp] = acc + bd[warp];
    }
    __syncthreads();

    if (t < N_MIX) {
        alpha[t] = expf(coef[t]);
        beta[t]  = expf(coef[N_MIX + t]);
        kap[t]   = kappa_prev[t] + expf(coef[2 * N_MIX + t]);
    }
    __syncthreads();

    if (t < CHAR_LEN) {
        float u = (float)(t + 1);
        float p = 0.f;
        #pragma unroll
        for (int m = 0; m < N_MIX; ++m) {
            float d = kap[m] - u;
            p += alpha[m] * expf(-beta[m] * d * d);
        }
        phi[t] = p;
    }
    __syncthreads();

    // w[v] = phi @ sentence[:, v]
    if (t < VOCAB) {
        float acc = 0.f;
        for (int u2 = 0; u2 < CHAR_LEN; ++u2)
            acc += phi[u2] * sentence[u2 * VOCAB + t];
        g_x2[3 + t] = acc;
        g_x3[3 + t] = acc;
    }
}

// ---------------- launch ----------------
extern "C" void kernel_launch(void* const* d_in, const int* in_sizes, int n_in,
                              void* d_out, int out_size)
{
    const float* inputs     = (const float*)d_in[0];
    const float* h1_in      = (const float*)d_in[1];
    const float* c1_in      = (const float*)d_in[2];
    const float* h2_in      = (const float*)d_in[3];
    const float* c2_in      = (const float*)d_in[4];
    const float* h3_in      = (const float*)d_in[5];
    const float* c3_in      = (const float*)d_in[6];
    const float* w_prev     = (const float*)d_in[7];
    const float* kappa_prev = (const float*)d_in[8];
    const float* sentence   = (const float*)d_in[9];
    const float* W1 = (const float*)d_in[10];
    const float* U1 = (const float*)d_in[11];
    const float* b1 = (const float*)d_in[12];
    const float* Wd = (const float*)d_in[13];
    const float* bd = (const float*)d_in[14];
    const float* W2 = (const float*)d_in[15];
    const float* U2 = (const float*)d_in[16];
    const float* b2 = (const float*)d_in[17];
    const float* W3 = (const float*)d_in[18];
    const float* U3 = (const float*)d_in[19];
    const float* b3 = (const float*)d_in[20];
    float* out = (float*)d_out;

    float *x1p, *x2p, *x3p;
    cudaGetSymbolAddress((void**)&x1p, g_x1);
    cudaGetSymbolAddress((void**)&x2p, g_x2);
    cudaGetSymbolAddress((void**)&x3p, g_x3);

    dim3 ggrid(12, NSPLIT);   // 12 column tiles (128 thr * 4 cols) x 32 k-splits

    prep_kernel<<<1, 128>>>(inputs, w_prev);

    // LSTM 1: z = [inputs,w_prev]@W1 + h1@U1
    gemv_kernel<<<ggrid, 128>>>(W1, x1p, 3 + VOCAB, U1, h1_in, UNITS);
    gates_kernel<<<12, 128>>>(b1, c1_in, out, x2p + 3 + VOCAB);

    // attention window -> w into x2/x3 heads
    window_kernel<<<1, 960>>>(Wd, bd, kappa_prev, sentence);

    // LSTM 2: z = [inputs,w,h1n]@W2 + h2@U2
    gemv_kernel<<<ggrid, 128>>>(W2, x2p, 3 + VOCAB + UNITS, U2, h2_in, UNITS);
    gates_kernel<<<12, 128>>>(b2, c2_in, out + UNITS, x3p + 3 + VOCAB);

    // LSTM 3: z = [inputs,w,h2n]@W3 + h3@U3
    gemv_kernel<<<ggrid, 128>>>(W3, x3p, 3 + VOCAB + UNITS, U3, h3_in, UNITS);
    gates_kernel<<<12, 128>>>(b3, c3_in, out + 2 * UNITS, nullptr);
}

// round 2
// speedup vs baseline: 1.1296x; 1.1296x over previous
#include <cuda_runtime.h>
#include <math.h>

#define UNITS 1536
#define NZ (4 * UNITS)          // 6144 gate pre-activations per LSTM
#define NSPLIT 48               // k-splits per GEMV
#define CHAR_LEN 256
#define VOCAB 80
#define N_MIX 10
#define KA1 (3 + VOCAB)         // 83
#define KX  (3 + VOCAB + UNITS) // 1619

// ---------------- device scratch (no allocations allowed) ----------------
__device__ float g_part1[NSPLIT][NZ];   // chain partials (W1+U1, then W2, then W3)
__device__ float g_part2[NSPLIT][NZ];   // U2 @ h2 partials (independent)
__device__ float g_part3[NSPLIT][NZ];   // U3 @ h3 partials (independent)
__device__ float g_x1[KA1];             // [inputs, w_prev]
__device__ float g_x2[KX];              // [inputs, w, h1n]
__device__ float g_x3[KX];              // [inputs, w, h2n]

__device__ __forceinline__ float sigf(float x) { return 1.0f / (1.0f + expf(-x)); }

// ---------------- tiny prep ----------------
__global__ void prep_kernel(const float* __restrict__ inputs,
                            const float* __restrict__ w_prev) {
    int t = threadIdx.x;
    if (t < 3) { g_x1[t] = inputs[t]; g_x2[t] = inputs[t]; g_x3[t] = inputs[t]; }
    if (t < VOCAB) g_x1[3 + t] = w_prev[t];
}

// ---------------- split-K GEMV body over two stacked segments ----------------
// Each thread owns one float4 column group; warp reads 512B contiguous per k-row.
__device__ __forceinline__ void gemv_body(
    const float* __restrict__ A, const float* __restrict__ xa, int Ka,
    const float* __restrict__ B, const float* __restrict__ xb, int Kb,
    float* __restrict__ part)
{
    int col = blockIdx.x * blockDim.x + threadIdx.x;   // float4 column 0..1535
    int split = blockIdx.y;
    int Kt = Ka + Kb;
    int k0 = (Kt * split) / NSPLIT;
    int k1 = (Kt * (split + 1)) / NSPLIT;

    float4 acc = make_float4(0.f, 0.f, 0.f, 0.f);
    int k = k0;
    int ka_end = (k1 < Ka) ? k1 : Ka;

    #pragma unroll 4
    for (; k < ka_end; ++k) {
        float xv = __ldg(xa + k);
        float4 r = *reinterpret_cast<const float4*>(A + (size_t)k * NZ + col * 4);
        acc.x += xv * r.x; acc.y += xv * r.y; acc.z += xv * r.z; acc.w += xv * r.w;
    }
    #pragma unroll 4
    for (; k < k1; ++k) {
        int kb = k - Ka;
        float xv = __ldg(xb + kb);
        float4 r = *reinterpret_cast<const float4*>(B + (size_t)kb * NZ + col * 4);
        acc.x += xv * r.x; acc.y += xv * r.y; acc.z += xv * r.z; acc.w += xv * r.w;
    }
    *reinterpret_cast<float4*>(part + (size_t)split * NZ + col * 4) = acc;
}

// Mega kernel: all GEMV work independent of the serial chain, in one launch.
// z=0: W1@x1 + U1@h1 -> part1;  z=1: U2@h2 -> part2;  z=2: U3@h3 -> part3.
__global__ void __launch_bounds__(128) mega_gemv_kernel(
    const float* __restrict__ W1, const float* __restrict__ U1, const float* __restrict__ h1,
    const float* __restrict__ U2, const float* __restrict__ h2,
    const float* __restrict__ U3, const float* __restrict__ h3)
{
    int z = blockIdx.z;
    if (z == 0)      gemv_body(W1, g_x1, KA1, U1, h1, UNITS, &g_part1[0][0]);
    else if (z == 1) gemv_body(U2, h2, UNITS, nullptr, nullptr, 0, &g_part2[0][0]);
    else             gemv_body(U3, h3, UNITS, nullptr, nullptr, 0, &g_part3[0][0]);
}

// Serial-chain GEMV: single matrix (W2 or W3) times assembled x -> part1.
__global__ void __launch_bounds__(128) chain_gemv_kernel(
    const float* __restrict__ A, const float* __restrict__ xa)
{
    gemv_body(A, xa, KX, nullptr, nullptr, 0, &g_part1[0][0]);
}

// ---------------- reduce partials + LSTM gates ----------------
// 48 blocks x 128 threads: block handles 32 units; 4 split-subgroups per unit.
__global__ void __launch_bounds__(128) gates_kernel(
    const float* __restrict__ b, const float* __restrict__ c_in,
    const float* __restrict__ pB,              // second partial set or nullptr
    float* __restrict__ out_h, float* __restrict__ xnext)
{
    __shared__ float red[4][32][4];
    int ul = threadIdx.x & 31;
    int sg = threadIdx.x >> 5;
    int u  = blockIdx.x * 32 + ul;

    float s0 = 0.f, s1 = 0.f, s2 = 0.f, s3 = 0.f;
    const float* pA = &g_part1[0][0];
    for (int s = sg; s < NSPLIT; s += 4) {
        const float* row = pA + (size_t)s * NZ;
        s0 += row[u];
        s1 += row[u + UNITS];
        s2 += row[u + 2 * UNITS];
        s3 += row[u + 3 * UNITS];
    }
    if (pB) {
        for (int s = sg; s < NSPLIT; s += 4) {
            const float* row = pB + (size_t)s * NZ;
            s0 += row[u];
            s1 += row[u + UNITS];
            s2 += row[u + 2 * UNITS];
            s3 += row[u + 3 * UNITS];
        }
    }
    red[sg][ul][0] = s0; red[sg][ul][1] = s1; red[sg][ul][2] = s2; red[sg][ul][3] = s3;
    __syncthreads();

    if (sg == 0) {
        float zi = b[u]             + red[0][ul][0] + red[1][ul][0] + red[2][ul][0] + red[3][ul][0];
        float zf = b[u + UNITS]     + red[0][ul][1] + red[1][ul][1] + red[2][ul][1] + red[3][ul][1];
        float zg = b[u + 2 * UNITS] + red[0][ul][2] + red[1][ul][2] + red[2][ul][2] + red[3][ul][2];
        float zo = b[u + 3 * UNITS] + red[0][ul][3] + red[1][ul][3] + red[2][ul][3] + red[3][ul][3];
        float c = sigf(zf) * c_in[u] + sigf(zi) * tanhf(zg);
        float h = sigf(zo) * tanhf(c);
        out_h[u] = h;
        if (xnext) xnext[u] = h;
    }
}

// ---------------- attention window (single block, 512 threads, coalesced) ----
__global__ void __launch_bounds__(512) window_kernel(
    const float* __restrict__ Wd, const float* __restrict__ bd,
    const float* __restrict__ kappa_prev, const float* __restrict__ sentence)
{
    __shared__ float wsum[16][30];
    __shared__ float coef[30];
    __shared__ float alpha[N_MIX], beta[N_MIX], kap[N_MIX];
    __shared__ float phi[CHAR_LEN];

    const float* h1 = g_x2 + KA1;   // h1n lives in x2 tail
    int t = threadIdx.x;
    int warp = t >> 5, lane = t & 31;

    // coef = h1n @ Wd + bd, with contiguous Wd row reads per thread
    float acc[30];
    #pragma unroll
    for (int j = 0; j < 30; ++j) acc[j] = 0.f;
    for (int k = t; k < UNITS; k += 512) {
        float hv = h1[k];
        const float* wr = Wd + (size_t)k * 30;
        #pragma unroll
        for (int j = 0; j < 30; ++j) acc[j] += hv * wr[j];
    }
    #pragma unroll
    for (int j = 0; j < 30; ++j) {
        float v = acc[j];
        #pragma unroll
        for (int o = 16; o; o >>= 1) v += __shfl_down_sync(0xffffffffu, v, o);
        if (lane == 0) wsum[warp][j] = v;
    }
    __syncthreads();
    if (t < 30) {
        float s = bd[t];
        #pragma unroll
        for (int w = 0; w < 16; ++w) s += wsum[w][t];
        coef[t] = s;
    }
    __syncthreads();

    if (t < N_MIX) {
        alpha[t] = expf(coef[t]);
        beta[t]  = expf(coef[N_MIX + t]);
        kap[t]   = kappa_prev[t] + expf(coef[2 * N_MIX + t]);
    }
    __syncthreads();

    if (t < CHAR_LEN) {
        float u = (float)(t + 1);
        float p = 0.f;
        #pragma unroll
        for (int m = 0; m < N_MIX; ++m) {
            float d = kap[m] - u;
            p += alpha[m] * expf(-beta[m] * d * d);
        }
        phi[t] = p;
    }
    __syncthreads();

    // w[v] = phi @ sentence[:, v]  -> heads of x2 and x3
    if (t < VOCAB) {
        float s = 0.f;
        #pragma unroll 8
        for (int u2 = 0; u2 < CHAR_LEN; ++u2)
            s += phi[u2] * sentence[u2 * VOCAB + t];
        g_x2[3 + t] = s;
        g_x3[3 + t] = s;
    }
}

// ---------------- launch ----------------
extern "C" void kernel_launch(void* const* d_in, const int* in_sizes, int n_in,
                              void* d_out, int out_size)
{
    const float* inputs     = (const float*)d_in[0];
    const float* h1_in      = (const float*)d_in[1];
    const float* c1_in      = (const float*)d_in[2];
    const float* h2_in      = (const float*)d_in[3];
    const float* c2_in      = (const float*)d_in[4];
    const float* h3_in      = (const float*)d_in[5];
    const float* c3_in      = (const float*)d_in[6];
    const float* w_prev     = (const float*)d_in[7];
    const float* kappa_prev = (const float*)d_in[8];
    const float* sentence   = (const float*)d_in[9];
    const float* W1 = (const float*)d_in[10];
    const float* U1 = (const float*)d_in[11];
    const float* b1 = (const float*)d_in[12];
    const float* Wd = (const float*)d_in[13];
    const float* bd = (const float*)d_in[14];
    const float* W2 = (const float*)d_in[15];
    const float* U2 = (const float*)d_in[16];
    const float* b2 = (const float*)d_in[17];
    const float* W3 = (const float*)d_in[18];
    const float* U3 = (const float*)d_in[19];
    const float* b3 = (const float*)d_in[20];
    float* out = (float*)d_out;

    float *x2p, *x3p, *p2p, *p3p;
    cudaGetSymbolAddress((void**)&x2p, g_x2);
    cudaGetSymbolAddress((void**)&x3p, g_x3);
    cudaGetSymbolAddress((void**)&p2p, g_part2);
    cudaGetSymbolAddress((void**)&p3p, g_part3);

    prep_kernel<<<1, 128>>>(inputs, w_prev);

    // All chain-independent GEMV traffic in one DRAM-saturating launch:
    // part1 = W1@x1 + U1@h1 ; part2 = U2@h2 ; part3 = U3@h3
    mega_gemv_kernel<<<dim3(12, NSPLIT, 3), 128>>>(W1, U1, h1_in, U2, h2_in, U3, h3_in);

    // LSTM 1 gates -> h1n (also into x2 tail)
    gates_kernel<<<48, 128>>>(b1, c1_in, nullptr, out, x2p + KA1);

    // attention window -> w into x2/x3 heads
    window_kernel<<<1, 512>>>(Wd, bd, kappa_prev, sentence);

    // LSTM 2: part1 = W2 @ x2 ; gates reduce part1 + part2(U2@h2)
    chain_gemv_kernel<<<dim3(12, NSPLIT), 128>>>(W2, x2p);
    gates_kernel<<<48, 128>>>(b2, c2_in, p2p, out + UNITS, x3p + KA1);

    // LSTM 3: part1 = W3 @ x3 ; gates reduce part1 + part3(U3@h3)
    chain_gemv_kernel<<<dim3(12, NSPLIT), 128>>>(W3, x3p);
    gates_kernel<<<48, 128>>>(b3, c3_in, p3p, out + 2 * UNITS, nullptr);
}

// round 3
// speedup vs baseline: 1.4127x; 1.2507x over previous
#include <cuda_runtime.h>
#include <math.h>

#define UNITS 1536
#define NZ (4 * UNITS)          // 6144 gate pre-activations per LSTM
#define NSPLIT 48               // k-splits per GEMV
#define CHAR_LEN 256
#define VOCAB 80
#define N_MIX 10
#define KA1 (3 + VOCAB)         // 83
#define KX  (3 + VOCAB + UNITS) // 1619

// ---------------- device scratch (no allocations allowed) ----------------
__device__ float g_part1[NSPLIT][NZ];   // chain partials (W1+U1, then W2, then W3)
__device__ float g_part2[NSPLIT][NZ];   // U2 @ h2 partials (independent)
__device__ float g_part3[NSPLIT][NZ];   // U3 @ h3 partials (independent)
__device__ float g_coefpart[48][30];    // h1n @ Wd partial sums (from gates1 blocks)
__device__ float g_x2[KX];              // [inputs, w, h1n]
__device__ float g_x3[KX];              // [inputs, w, h2n]

__device__ __forceinline__ float sigf(float x) { return 1.0f / (1.0f + expf(-x)); }

// ---------------- split-K GEMV body: three stacked segments ----------------
// Mcat = [A0 (K0) ; A1 (K1, rows at A0 + K0*NZ) ; B (Kb)], x = [x0; x1; xb].
// Each thread owns one float4 column group; warp reads 512B contiguous per k-row.
__device__ __forceinline__ void gemv_body3(
    const float* __restrict__ A, const float* __restrict__ x0, int K0,
    const float* __restrict__ x1, int K1,
    const float* __restrict__ B, const float* __restrict__ xb, int Kb,
    float* __restrict__ part)
{
    int col = blockIdx.x * blockDim.x + threadIdx.x;   // float4 column 0..1535
    int split = blockIdx.y;
    int Ka = K0 + K1;
    int Kt = Ka + Kb;
    int k0 = (Kt * split) / NSPLIT;
    int k1 = (Kt * (split + 1)) / NSPLIT;

    float4 acc = make_float4(0.f, 0.f, 0.f, 0.f);
    int k = k0;
    int ka_end = (k1 < Ka) ? k1 : Ka;

    #pragma unroll 8
    for (; k < ka_end; ++k) {
        float xv = (k < K0) ? __ldg(x0 + k) : __ldg(x1 + (k - K0));
        float4 r = *reinterpret_cast<const float4*>(A + (size_t)k * NZ + col * 4);
        acc.x += xv * r.x; acc.y += xv * r.y; acc.z += xv * r.z; acc.w += xv * r.w;
    }
    #pragma unroll 8
    for (; k < k1; ++k) {
        int kb = k - Ka;
        float xv = __ldg(xb + kb);
        float4 r = *reinterpret_cast<const float4*>(B + (size_t)kb * NZ + col * 4);
        acc.x += xv * r.x; acc.y += xv * r.y; acc.z += xv * r.z; acc.w += xv * r.w;
    }
    *reinterpret_cast<float4*>(part + (size_t)split * NZ + col * 4) = acc;
}

// Mega kernel: all GEMV work independent of the serial chain, in one launch.
// z=0: W1@[inputs,w_prev] + U1@h1 -> part1;  z=1: U2@h2 -> part2;  z=2: U3@h3 -> part3.
__global__ void __launch_bounds__(128) mega_gemv_kernel(
    const float* __restrict__ W1, const float* __restrict__ inputs,
    const float* __restrict__ w_prev, const float* __restrict__ U1,
    const float* __restrict__ h1,
    const float* __restrict__ U2, const float* __restrict__ h2,
    const float* __restrict__ U3, const float* __restrict__ h3)
{
    int z = blockIdx.z;
    if (z == 0)      gemv_body3(W1, inputs, 3, w_prev, VOCAB, U1, h1, UNITS, &g_part1[0][0]);
    else if (z == 1) gemv_body3(U2, h2, UNITS, nullptr, 0, nullptr, nullptr, 0, &g_part2[0][0]);
    else             gemv_body3(U3, h3, UNITS, nullptr, 0, nullptr, nullptr, 0, &g_part3[0][0]);
}

// Serial-chain GEMV: single matrix (W2 or W3) times assembled x -> part1.
__global__ void __launch_bounds__(128) chain_gemv_kernel(
    const float* __restrict__ A, const float* __restrict__ xa)
{
    gemv_body3(A, xa, KX, nullptr, 0, nullptr, nullptr, 0, &g_part1[0][0]);
}

// ---------------- reduce partials + LSTM gates (+ fused coef partials) -----
// 48 blocks x 128 threads: block handles 32 units; 4 split-subgroups per unit.
__global__ void __launch_bounds__(128) gates_kernel(
    const float* __restrict__ b, const float* __restrict__ c_in,
    const float* __restrict__ pB,              // second partial set or nullptr
    float* __restrict__ out_h, float* __restrict__ xnext,
    const float* __restrict__ Wd)              // non-null => emit coef partials
{
    __shared__ float red[4][32][4];
    __shared__ float hsh[32];
    __shared__ float csh[4][30];
    int t  = threadIdx.x;
    int ul = t & 31;
    int sg = t >> 5;
    int u  = blockIdx.x * 32 + ul;

    float s0 = 0.f, s1 = 0.f, s2 = 0.f, s3 = 0.f;
    const float* pA = &g_part1[0][0];
    for (int s = sg; s < NSPLIT; s += 4) {
        const float* row = pA + (size_t)s * NZ;
        s0 += row[u];
        s1 += row[u + UNITS];
        s2 += row[u + 2 * UNITS];
        s3 += row[u + 3 * UNITS];
    }
    if (pB) {
        for (int s = sg; s < NSPLIT; s += 4) {
            const float* row = pB + (size_t)s * NZ;
            s0 += row[u];
            s1 += row[u + UNITS];
            s2 += row[u + 2 * UNITS];
            s3 += row[u + 3 * UNITS];
        }
    }
    red[sg][ul][0] = s0; red[sg][ul][1] = s1; red[sg][ul][2] = s2; red[sg][ul][3] = s3;
    __syncthreads();

    if (sg == 0) {
        float zi = b[u]             + red[0][ul][0] + red[1][ul][0] + red[2][ul][0] + red[3][ul][0];
        float zf = b[u + UNITS]     + red[0][ul][1] + red[1][ul][1] + red[2][ul][1] + red[3][ul][1];
        float zg = b[u + 2 * UNITS] + red[0][ul][2] + red[1][ul][2] + red[2][ul][2] + red[3][ul][2];
        float zo = b[u + 3 * UNITS] + red[0][ul][3] + red[1][ul][3] + red[2][ul][3] + red[3][ul][3];
        float c = sigf(zf) * c_in[u] + sigf(zi) * tanhf(zg);
        float h = sigf(zo) * tanhf(c);
        out_h[u] = h;
        if (xnext) xnext[u] = h;
        hsh[ul] = h;
    }

    if (Wd) {
        __syncthreads();
        // 120 threads: j = t%30, unit-group g = t/30 (8 units each)
        if (t < 120) {
            int j = t % 30, g = t / 30;
            int ub = blockIdx.x * 32 + g * 8;
            float s = 0.f;
            #pragma unroll
            for (int i = 0; i < 8; ++i)
                s += hsh[g * 8 + i] * __ldg(Wd + (size_t)(ub + i) * 30 + j);
            csh[g][j] = s;
        }
        __syncthreads();
        if (t < 30)
            g_coefpart[blockIdx.x][t] = csh[0][t] + csh[1][t] + csh[2][t] + csh[3][t];
    }
}

// ---------------- window finish (1 block, 512 threads) ----------------------
// Reduces coef partials, computes alpha/beta/kappa/phi, then w = phi@sentence
// with 16 warps split over chars. Also writes [inputs, w] heads of x2/x3.
__global__ void __launch_bounds__(512) window_finish_kernel(
    const float* __restrict__ bd, const float* __restrict__ kappa_prev,
    const float* __restrict__ sentence, const float* __restrict__ inputs)
{
    __shared__ float coef[30];
    __shared__ float alpha[N_MIX], beta[N_MIX], kap[N_MIX];
    __shared__ float phi[CHAR_LEN];
    __shared__ float wpart[16][VOCAB];

    int t = threadIdx.x;
    int warp = t >> 5, lane = t & 31;

    if (t < 3) { g_x2[t] = inputs[t]; g_x3[t] = inputs[t]; }
    if (t < 30) {
        float s = bd[t];
        #pragma unroll
        for (int blk = 0; blk < 48; ++blk) s += g_coefpart[blk][t];
        coef[t] = s;
    }
    __syncthreads();
    if (t < N_MIX) {
        alpha[t] = expf(coef[t]);
        beta[t]  = expf(coef[N_MIX + t]);
        kap[t]   = kappa_prev[t] + expf(coef[2 * N_MIX + t]);
    }
    __syncthreads();
    if (t < CHAR_LEN) {
        float u = (float)(t + 1);
        float p = 0.f;
        #pragma unroll
        for (int m = 0; m < N_MIX; ++m) {
            float d = kap[m] - u;
            p += alpha[m] * expf(-beta[m] * d * d);
        }
        phi[t] = p;
    }
    __syncthreads();

    // Each warp handles 16 chars; lanes cover the 80 vocab columns (coalesced).
    {
        float a0 = 0.f, a1 = 0.f, a2 = 0.f;
        #pragma unroll
        for (int cc = 0; cc < 16; ++cc) {
            int c = warp * 16 + cc;
            float pv = phi[c];
            const float* row = sentence + (size_t)c * VOCAB;
            a0 += pv * __ldg(row + lane);
            a1 += pv * __ldg(row + 32 + lane);
            if (lane < 16) a2 += pv * __ldg(row + 64 + lane);
        }
        wpart[warp][lane]      = a0;
        wpart[warp][lane + 32] = a1;
        if (lane < 16) wpart[warp][lane + 64] = a2;
    }
    __syncthreads();
    if (t < VOCAB) {
        float s = 0.f;
        #pragma unroll
        for (int w = 0; w < 16; ++w) s += wpart[w][t];
        g_x2[3 + t] = s;
        g_x3[3 + t] = s;
    }
}

// ---------------- launch ----------------
extern "C" void kernel_launch(void* const* d_in, const int* in_sizes, int n_in,
                              void* d_out, int out_size)
{
    const float* inputs     = (const float*)d_in[0];
    const float* h1_in      = (const float*)d_in[1];
    const float* c1_in      = (const float*)d_in[2];
    const float* h2_in      = (const float*)d_in[3];
    const float* c2_in      = (const float*)d_in[4];
    const float* h3_in      = (const float*)d_in[5];
    const float* c3_in      = (const float*)d_in[6];
    const float* w_prev     = (const float*)d_in[7];
    const float* kappa_prev = (const float*)d_in[8];
    const float* sentence   = (const float*)d_in[9];
    const float* W1 = (const float*)d_in[10];
    const float* U1 = (const float*)d_in[11];
    const float* b1 = (const float*)d_in[12];
    const float* Wd = (const float*)d_in[13];
    const float* bd = (const float*)d_in[14];
    const float* W2 = (const float*)d_in[15];
    const float* U2 = (const float*)d_in[16];
    const float* b2 = (const float*)d_in[17];
    const float* W3 = (const float*)d_in[18];
    const float* U3 = (const float*)d_in[19];
    const float* b3 = (const float*)d_in[20];
    float* out = (float*)d_out;

    float *x2p, *x3p, *p2p, *p3p;
    cudaGetSymbolAddress((void**)&x2p, g_x2);
    cudaGetSymbolAddress((void**)&x3p, g_x3);
    cudaGetSymbolAddress((void**)&p2p, g_part2);
    cudaGetSymbolAddress((void**)&p3p, g_part3);

    // All chain-independent GEMV traffic in one DRAM-saturating launch:
    // part1 = W1@[inputs,w_prev] + U1@h1 ; part2 = U2@h2 ; part3 = U3@h3
    mega_gemv_kernel<<<dim3(12, NSPLIT, 3), 128>>>(
        W1, inputs, w_prev, U1, h1_in, U2, h2_in, U3, h3_in);

    // LSTM 1 gates -> h1n (into out + x2 tail) + fused coef partials
    gates_kernel<<<48, 128>>>(b1, c1_in, nullptr, out, x2p + KA1, Wd);

    // finish window -> w (+inputs) into x2/x3 heads
    window_finish_kernel<<<1, 512>>>(bd, kappa_prev, sentence, inputs);

    // LSTM 2: part1 = W2 @ x2 ; gates reduce part1 + part2(U2@h2)
    chain_gemv_kernel<<<dim3(12, NSPLIT), 128>>>(W2, x2p);
    gates_kernel<<<48, 128>>>(b2, c2_in, p2p, out + UNITS, x3p + KA1, nullptr);

    // LSTM 3: part1 = W3 @ x3 ; gates reduce part1 + part3(U3@h3)
    chain_gemv_kernel<<<dim3(12, NSPLIT), 128>>>(W3, x3p);
    gates_kernel<<<48, 128>>>(b3, c3_in, p3p, out + 2 * UNITS, nullptr, nullptr);
}

// round 4
// speedup vs baseline: 1.7388x; 1.2308x over previous
#include <cuda_runtime.h>
#include <math.h>

#define UNITS 1536
#define NZ (4 * UNITS)          // 6144 gate pre-activations per LSTM
#define NSPLIT 96               // k-splits per GEMV
#define CHAR_LEN 256
#define VOCAB 80
#define N_MIX 10
#define KA1 (3 + VOCAB)         // 83
#define KX  (3 + VOCAB + UNITS) // 1619

// ---------------- device scratch (no allocations allowed) ----------------
__device__ float g_part1[NSPLIT][NZ];   // chain partials (W1+U1, then W2, then W3)
__device__ float g_part2[NSPLIT][NZ];   // U2 @ h2 partials (independent)
__device__ float g_part3[NSPLIT][NZ];   // U3 @ h3 partials (independent)
__device__ float g_coefpart[48][30];    // h1n @ Wd partial sums (from gates1 blocks)
__device__ float g_x2[KX];              // [inputs, w, h1n]
__device__ float g_x3[KX];              // [inputs, w, h2n]

__device__ __forceinline__ float sigf(float x) { return 1.0f / (1.0f + expf(-x)); }

// ---------------- split-K GEMV core -----------------------------------------
// Concatenated operand: rows [0,K0) from x0 via matrix A, [K0,K0+K1) from x1
// via A (contiguous rows), [K0+K1, +Kb) from xb via matrix B.
// Each thread owns one float4 column group. 8-deep explicit load batching:
// 8 independent row LDG.128s issued back-to-back before any FMA.
__device__ __forceinline__ float xval(
    const float* __restrict__ x0, int K0,
    const float* __restrict__ x1, int K1,
    const float* __restrict__ xb, int k)
{
    if (k < K0) return __ldg(x0 + k);
    if (k < K0 + K1) return __ldg(x1 + (k - K0));
    return __ldg(xb + (k - K0 - K1));
}

__device__ __forceinline__ void gemv_core(
    const float* __restrict__ A, const float* __restrict__ x0, int K0,
    const float* __restrict__ x1, int K1,
    const float* __restrict__ B, const float* __restrict__ xb, int Kb,
    float* __restrict__ part)
{
    int col = blockIdx.x * blockDim.x + threadIdx.x;   // float4 column 0..1535
    int split = blockIdx.y;
    int Ka = K0 + K1;
    int Kt = Ka + Kb;
    int k0 = (Kt * split) / NSPLIT;
    int k1 = (Kt * (split + 1)) / NSPLIT;

    const float* Acol = A + (size_t)col * 4;
    const float* Bcol = B ? (B + (size_t)col * 4) : nullptr;

    float4 acc = make_float4(0.f, 0.f, 0.f, 0.f);
    int k = k0;

    for (; k + 8 <= k1; k += 8) {
        float xv[8];
        float4 r[8];
        #pragma unroll
        for (int i = 0; i < 8; ++i)
            xv[i] = xval(x0, K0, x1, K1, xb, k + i);
        #pragma unroll
        for (int i = 0; i < 8; ++i) {
            int kk = k + i;
            const float* rp = (kk < Ka) ? (Acol + (size_t)kk * NZ)
                                        : (Bcol + (size_t)(kk - Ka) * NZ);
            r[i] = *reinterpret_cast<const float4*>(rp);
        }
        #pragma unroll
        for (int i = 0; i < 8; ++i) {
            acc.x += xv[i] * r[i].x; acc.y += xv[i] * r[i].y;
            acc.z += xv[i] * r[i].z; acc.w += xv[i] * r[i].w;
        }
    }
    for (; k < k1; ++k) {
        float xv = xval(x0, K0, x1, K1, xb, k);
        const float* rp = (k < Ka) ? (Acol + (size_t)k * NZ)
                                   : (Bcol + (size_t)(k - Ka) * NZ);
        float4 r = *reinterpret_cast<const float4*>(rp);
        acc.x += xv * r.x; acc.y += xv * r.y; acc.z += xv * r.z; acc.w += xv * r.w;
    }
    *reinterpret_cast<float4*>(part + (size_t)split * NZ + col * 4) = acc;
}

// Mega kernel: all GEMV work independent of the serial chain.
// z=0: W1@[inputs,w_prev] + U1@h1 -> part1;  z=1: U2@h2 -> part2;  z=2: U3@h3 -> part3.
__global__ void __launch_bounds__(128) mega_gemv_kernel(
    const float* __restrict__ W1, const float* __restrict__ inputs,
    const float* __restrict__ w_prev, const float* __restrict__ U1,
    const float* __restrict__ h1,
    const float* __restrict__ U2, const float* __restrict__ h2,
    const float* __restrict__ U3, const float* __restrict__ h3)
{
    int z = blockIdx.z;
    if (z == 0)      gemv_core(W1, inputs, 3, w_prev, VOCAB, U1, h1, UNITS, &g_part1[0][0]);
    else if (z == 1) gemv_core(U2, h2, UNITS, nullptr, 0, nullptr, nullptr, 0, &g_part2[0][0]);
    else             gemv_core(U3, h3, UNITS, nullptr, 0, nullptr, nullptr, 0, &g_part3[0][0]);
}

// Serial-chain GEMV: single matrix (W2 or W3) times assembled x -> part1.
__global__ void __launch_bounds__(128) chain_gemv_kernel(
    const float* __restrict__ A, const float* __restrict__ xa)
{
    gemv_core(A, xa, KX, nullptr, 0, nullptr, nullptr, 0, &g_part1[0][0]);
}

// ---------------- reduce partials + LSTM gates (+ fused coef partials) -----
// 48 blocks x 256 threads: block handles 32 units; 8 split-subgroups per unit.
// Partials are L2-resident (just written); fully unrolled -> high MLP.
__global__ void __launch_bounds__(256) gates_kernel(
    const float* __restrict__ b, const float* __restrict__ c_in,
    const float* __restrict__ pB,              // second partial set or nullptr
    float* __restrict__ out_h, float* __restrict__ xnext,
    const float* __restrict__ Wd)              // non-null => emit coef partials
{
    __shared__ float red[8][32][4];
    __shared__ float hsh[32];
    __shared__ float csh[4][30];
    int t  = threadIdx.x;
    int ul = t & 31;
    int sg = t >> 5;                           // 0..7
    int u  = blockIdx.x * 32 + ul;

    float s0 = 0.f, s1 = 0.f, s2 = 0.f, s3 = 0.f;
    const float* pA = &g_part1[0][0];
    #pragma unroll
    for (int i = 0; i < NSPLIT / 8; ++i) {
        const float* row = pA + (size_t)(sg + i * 8) * NZ;
        s0 += row[u];
        s1 += row[u + UNITS];
        s2 += row[u + 2 * UNITS];
        s3 += row[u + 3 * UNITS];
    }
    if (pB) {
        #pragma unroll
        for (int i = 0; i < NSPLIT / 8; ++i) {
            const float* row = pB + (size_t)(sg + i * 8) * NZ;
            s0 += row[u];
            s1 += row[u + UNITS];
            s2 += row[u + 2 * UNITS];
            s3 += row[u + 3 * UNITS];
        }
    }
    red[sg][ul][0] = s0; red[sg][ul][1] = s1; red[sg][ul][2] = s2; red[sg][ul][3] = s3;
    __syncthreads();

    if (sg == 0) {
        float zi = b[u], zf = b[u + UNITS], zg = b[u + 2 * UNITS], zo = b[u + 3 * UNITS];
        #pragma unroll
        for (int g = 0; g < 8; ++g) {
            zi += red[g][ul][0]; zf += red[g][ul][1];
            zg += red[g][ul][2]; zo += red[g][ul][3];
        }
        float c = sigf(zf) * c_in[u] + sigf(zi) * tanhf(zg);
        float h = sigf(zo) * tanhf(c);
        out_h[u] = h;
        if (xnext) xnext[u] = h;
        hsh[ul] = h;
    }

    if (Wd) {
        __syncthreads();
        // 120 threads: j = t%30, unit-group g = t/30 (8 units each)
        if (t < 120) {
            int j = t % 30, g = t / 30;
            int ub = blockIdx.x * 32 + g * 8;
            float s = 0.f;
            #pragma unroll
            for (int i = 0; i < 8; ++i)
                s += hsh[g * 8 + i] * __ldg(Wd + (size_t)(ub + i) * 30 + j);
            csh[g][j] = s;
        }
        __syncthreads();
        if (t < 30)
            g_coefpart[blockIdx.x][t] = csh[0][t] + csh[1][t] + csh[2][t] + csh[3][t];
    }
}

// ---------------- window finish (1 block, 512 threads) ----------------------
__global__ void __launch_bounds__(512) window_finish_kernel(
    const float* __restrict__ bd, const float* __restrict__ kappa_prev,
    const float* __restrict__ sentence, const float* __restrict__ inputs)
{
    __shared__ float coef[30];
    __shared__ float alpha[N_MIX], beta[N_MIX], kap[N_MIX];
    __shared__ float phi[CHAR_LEN];
    __shared__ float wpart[16][VOCAB];

    int t = threadIdx.x;
    int warp = t >> 5, lane = t & 31;

    if (t < 3) { g_x2[t] = inputs[t]; g_x3[t] = inputs[t]; }
    if (t < 30) {
        float s = bd[t];
        #pragma unroll
        for (int blk = 0; blk < 48; ++blk) s += g_coefpart[blk][t];
        coef[t] = s;
    }
    __syncthreads();
    if (t < N_MIX) {
        alpha[t] = expf(coef[t]);
        beta[t]  = expf(coef[N_MIX + t]);
        kap[t]   = kappa_prev[t] + expf(coef[2 * N_MIX + t]);
    }
    __syncthreads();
    if (t < CHAR_LEN) {
        float u = (float)(t + 1);
        float p = 0.f;
        #pragma unroll
        for (int m = 0; m < N_MIX; ++m) {
            float d = kap[m] - u;
            p += alpha[m] * expf(-beta[m] * d * d);
        }
        phi[t] = p;
    }
    __syncthreads();

    // Each warp handles 16 chars; lanes cover the 80 vocab columns (coalesced).
    {
        float a0 = 0.f, a1 = 0.f, a2 = 0.f;
        #pragma unroll
        for (int cc = 0; cc < 16; ++cc) {
            int c = warp * 16 + cc;
            float pv = phi[c];
            const float* row = sentence + (size_t)c * VOCAB;
            a0 += pv * __ldg(row + lane);
            a1 += pv * __ldg(row + 32 + lane);
            if (lane < 16) a2 += pv * __ldg(row + 64 + lane);
        }
        wpart[warp][lane]      = a0;
        wpart[warp][lane + 32] = a1;
        if (lane < 16) wpart[warp][lane + 64] = a2;
    }
    __syncthreads();
    if (t < VOCAB) {
        float s = 0.f;
        #pragma unroll
        for (int w = 0; w < 16; ++w) s += wpart[w][t];
        g_x2[3 + t] = s;
        g_x3[3 + t] = s;
    }
}

// ---------------- launch ----------------
extern "C" void kernel_launch(void* const* d_in, const int* in_sizes, int n_in,
                              void* d_out, int out_size)
{
    const float* inputs     = (const float*)d_in[0];
    const float* h1_in      = (const float*)d_in[1];
    const float* c1_in      = (const float*)d_in[2];
    const float* h2_in      = (const float*)d_in[3];
    const float* c2_in      = (const float*)d_in[4];
    const float* h3_in      = (const float*)d_in[5];
    const float* c3_in      = (const float*)d_in[6];
    const float* w_prev     = (const float*)d_in[7];
    const float* kappa_prev = (const float*)d_in[8];
    const float* sentence   = (const float*)d_in[9];
    const float* W1 = (const float*)d_in[10];
    const float* U1 = (const float*)d_in[11];
    const float* b1 = (const float*)d_in[12];
    const float* Wd = (const float*)d_in[13];
    const float* bd = (const float*)d_in[14];
    const float* W2 = (const float*)d_in[15];
    const float* U2 = (const float*)d_in[16];
    const float* b2 = (const float*)d_in[17];
    const float* W3 = (const float*)d_in[18];
    const float* U3 = (const float*)d_in[19];
    const float* b3 = (const float*)d_in[20];
    float* out = (float*)d_out;

    float *x2p, *x3p, *p2p, *p3p;
    cudaGetSymbolAddress((void**)&x2p, g_x2);
    cudaGetSymbolAddress((void**)&x3p, g_x3);
    cudaGetSymbolAddress((void**)&p2p, g_part2);
    cudaGetSymbolAddress((void**)&p3p, g_part3);

    // All chain-independent GEMV traffic in one DRAM-saturating launch:
    // part1 = W1@[inputs,w_prev] + U1@h1 ; part2 = U2@h2 ; part3 = U3@h3
    mega_gemv_kernel<<<dim3(12, NSPLIT, 3), 128>>>(
        W1, inputs, w_prev, U1, h1_in, U2, h2_in, U3, h3_in);

    // LSTM 1 gates -> h1n (into out + x2 tail) + fused coef partials
    gates_kernel<<<48, 256>>>(b1, c1_in, nullptr, out, x2p + KA1, Wd);

    // finish window -> w (+inputs) into x2/x3 heads
    window_finish_kernel<<<1, 512>>>(bd, kappa_prev, sentence, inputs);

    // LSTM 2: part1 = W2 @ x2 ; gates reduce part1 + part2(U2@h2)
    chain_gemv_kernel<<<dim3(12, NSPLIT), 128>>>(W2, x2p);
    gates_kernel<<<48, 256>>>(b2, c2_in, p2p, out + UNITS, x3p + KA1, nullptr);

    // LSTM 3: part1 = W3 @ x3 ; gates reduce part1 + part3(U3@h3)
    chain_gemv_kernel<<<dim3(12, NSPLIT), 128>>>(W3, x3p);
    gates_kernel<<<48, 256>>>(b3, c3_in, p3p, out + 2 * UNITS, nullptr, nullptr);
}